// round 16
// baseline (speedup 1.0000x reference)
#include <cuda_runtime.h>
#include <cuda_bf16.h>

#define BB 4
#define SS 1024
#define DD 2048
#define RPB 8                  // rows per block
#define KS 2                   // K-split factor
#define KH (DD / KS)           // 1024 floats per K-half
#define NBLK (DD / RPB * KS)   // 512 blocks

// K-split partials (allocation-free rule: __device__ globals; device refs only).
// Every element written each launch -> no init needed, replay-deterministic.
__device__ float g_vp[KS][BB][DD];
__device__ float g_op[KS][BB][DD];

__device__ __forceinline__ float4 f4add(float4 a, float4 b) {
    return make_float4(a.x + b.x, a.y + b.y, a.z + b.z, a.w + b.w);
}

// Partial GEMV: block (kc, rg) computes, for its 8 rows and K-half kc,
//   yp[kc][b][row] = sum_{k in half} x[b][k] * W[row][k]
// Warp w owns the 128-float slice at kc*1024 + w*128; lane l holds 1 float4
// per row / per batch. 12 independent LDG.128 per lane (8 W + 4 x), x in
// registers, W direct from global (no smem round-trip).
// STAGE 0: x = cond, y = g_vp.  STAGE 1: x = g_vp[0]+g_vp[1]+bv, y = g_op.
template<int STAGE>
__global__ __launch_bounds__(256) void gemv_ks(const float* __restrict__ W,
                                               const float* __restrict__ cond,
                                               const float* __restrict__ bv) {
    __shared__ float pr[8][32];    // per-warp reduced outputs

    const int tid  = threadIdx.x;
    const int wid  = tid >> 5;
    const int lane = tid & 31;
    const int kc   = blockIdx.x & (KS - 1);
    const int rg   = blockIdx.x >> 1;
    const int r0   = rg * RPB;
    const int ka   = kc * KH + wid * 128 + lane * 4;   // float offset

    // x into registers: 4 batches x 1 float4.
    float4 xa[BB];
    #pragma unroll
    for (int b = 0; b < BB; ++b) {
        if (STAGE == 0) {
            xa[b] = *(const float4*)(cond + b * DD + ka);
        } else {
            const float4 v0 = *(const float4*)(&g_vp[0][b][ka]);
            const float4 v1 = *(const float4*)(&g_vp[1][b][ka]);
            const float4 bb = *(const float4*)(bv + ka);
            xa[b] = f4add(f4add(v0, v1), bb);
        }
    }

    // 8 W float4s (one per row), independent LDGs.
    float4 wa[8];
    #pragma unroll
    for (int r = 0; r < 8; ++r)
        wa[r] = *(const float4*)(W + (size_t)(r0 + r) * DD + ka);

    // acc[r*4+b]: 8 rows x 4 batches per-lane partial dots.
    float acc[32];
    #pragma unroll
    for (int r = 0; r < 8; ++r) {
        #pragma unroll
        for (int b = 0; b < BB; ++b) {
            acc[r * 4 + b] = wa[r].x * xa[b].x + wa[r].y * xa[b].y +
                             wa[r].z * xa[b].z + wa[r].w * xa[b].w;
        }
    }

    // Butterfly: 32 values/lane -> lane l holds warp-sum for output
    // (row r0 + (l>>2), batch l&3). Mapping verified in R7/R13.
    int L = 32;
    #pragma unroll
    for (int m = 16; m >= 1; m >>= 1) {
        L >>= 1;
        const bool up = (lane & m) != 0;
        #pragma unroll
        for (int j = 0; j < L; ++j) {
            const float send = up ? acc[j] : acc[j + L];
            const float recv = __shfl_xor_sync(0xffffffffu, send, m);
            acc[j] = (up ? acc[j + L] : acc[j]) + recv;
        }
    }

    pr[wid][lane] = acc[0];
    __syncthreads();

    // Cross-warp combine (8 warps of this K-half) -> partial for this kc.
    if (tid < 32) {
        float s = pr[0][tid];
        #pragma unroll
        for (int w = 1; w < 8; ++w) s += pr[w][tid];
        const int row = r0 + (tid >> 2);
        const int b   = tid & 3;
        float* yp = (STAGE == 0) ? &g_vp[0][0][0] : &g_op[0][0][0];
        yp[((size_t)kc * BB + b) * DD + row] = s;
    }
}

// out[b][s][:] = g_op[0][b][:] + g_op[1][b][:] + bo, broadcast over s.
// Each owner thread loads once, stores 8 s-positions.
__global__ __launch_bounds__(256) void bcast_kernel(float4* __restrict__ out,
                                                    const float* __restrict__ bo) {
    const int t  = blockIdx.x * 256 + threadIdx.x;   // 256K threads
    const int d4 = t & 511;
    const int g  = t >> 9;
    const int b  = g >> 7;           // 0..3
    const int s8 = (g & 127) * 8;

    const float4* op  = (const float4*)g_op;         // [kc][b][512 f4]
    const float4* bo4 = (const float4*)bo;
    const float4 o = f4add(f4add(op[(0 * BB + b) * 512 + d4],
                                 op[(1 * BB + b) * 512 + d4]),
                           bo4[d4]);

    float4* dst = out + ((size_t)(b * SS + s8) * 512) + d4;
    #pragma unroll
    for (int i = 0; i < 8; ++i)
        dst[(size_t)i * 512] = o;
}

extern "C" void kernel_launch(void* const* d_in, const int* in_sizes, int n_in,
                              void* d_out, int out_size) {
    // Inputs: hidden_states, condition, Wq, bq, Wk, bk, Wv, bv, Wo, bo
    const float* cond = (const float*)d_in[1];
    const float* Wv   = (const float*)d_in[6];
    const float* bv   = (const float*)d_in[7];
    const float* Wo   = (const float*)d_in[8];
    const float* bo   = (const float*)d_in[9];
    float* out = (float*)d_out;

    gemv_ks<0><<<NBLK, 256>>>(Wv, cond, nullptr);
    gemv_ks<1><<<NBLK, 256>>>(Wo, nullptr, bv);
    bcast_kernel<<<(BB * SS * (DD / 4) / 8) / 256, 256>>>((float4*)out, bo);
}